// round 2
// baseline (speedup 1.0000x reference)
#include <cuda_runtime.h>

// nodal_MLP: gather(64 of 256 cols, gated) + MLP 64->100->100->100->1, fp32.
// Baseline strategy: weights resident in SMEM (broadcast LDS), 1 row/thread,
// accumulators in registers, activations ping-pong via padded per-thread SMEM.

constexpr int TPB   = 256;   // threads per block = rows per block
constexpr int A     = 64;    // adjacency / first-layer fan-in
constexpr int H     = 100;   // hidden width
constexpr int NNODE = 256;   // columns of data

// Shared-memory layout (float offsets)
constexpr int OFF_W1  = 0;                   // 64*100
constexpr int OFF_W2  = OFF_W1 + A * H;      // 100*100
constexpr int OFF_W3  = OFF_W2 + H * H;      // 100*100
constexpr int OFF_B1  = OFF_W3 + H * H;
constexpr int OFF_B2  = OFF_B1 + H;
constexpr int OFF_B3  = OFF_B2 + H;
constexpr int OFF_W4  = OFF_B3 + H;
constexpr int OFF_G   = OFF_W4 + H;          // gate[64]
constexpr int OFF_IDX = OFF_G + A;           // int idx[64] (stored in float slots)
constexpr int OFF_B4  = OFF_IDX + A;
constexpr int OFF_H   = OFF_B4 + 4;          // per-thread h buffer, stride H+1
constexpr int H_STRIDE = H + 1;              // 101: (t*101+j)&31 = (5t+j)&31 -> conflict-free
constexpr int SMEM_FLOATS = OFF_H + TPB * H_STRIDE;
constexpr int SMEM_BYTES  = SMEM_FLOATS * 4; // ~211 KB

static_assert(OFF_H % 4 == 0, "h buffer base must be 16B aligned");

__global__ void __launch_bounds__(TPB, 1) nodal_mlp_kernel(
    const float* __restrict__ data, const float* __restrict__ weights,
    const float* __restrict__ W1, const float* __restrict__ b1,
    const float* __restrict__ W2, const float* __restrict__ b2,
    const float* __restrict__ W3, const float* __restrict__ b3,
    const float* __restrict__ W4, const float* __restrict__ b4,
    const int* __restrict__ data_idx, const int* __restrict__ edge_dir,
    const int* __restrict__ weight_idx,
    float* __restrict__ out, int n_rows)
{
    extern __shared__ float s[];
    const int t = threadIdx.x;

    // Stage all parameters into SMEM
    for (int i = t; i < A * H; i += TPB) s[OFF_W1 + i] = W1[i];
    for (int i = t; i < H * H; i += TPB) s[OFF_W2 + i] = W2[i];
    for (int i = t; i < H * H; i += TPB) s[OFF_W3 + i] = W3[i];
    if (t < H) {
        s[OFF_B1 + t] = b1[t];
        s[OFF_B2 + t] = b2[t];
        s[OFF_B3 + t] = b3[t];
        s[OFF_W4 + t] = W4[t];
    }
    if (t < A) {
        ((int*)s)[OFF_IDX + t] = data_idx[t];
        float g = weights[weight_idx[t]] * (float)edge_dir[t];
        s[OFF_G + t] = g > 0.f ? g : 0.f;   // relu gate
    }
    if (t == 0) s[OFF_B4] = b4[0];
    __syncthreads();

    const int row = blockIdx.x * TPB + t;
    if (row >= n_rows) return;

    float* hp = s + OFF_H + t * H_STRIDE;   // per-thread private activation buffer
    const float* drow = data + (size_t)row * NNODE;

    // Gather + gate into SMEM buffer
    #pragma unroll
    for (int a = 0; a < A; a++) {
        int ix = ((const int*)s)[OFF_IDX + a];
        hp[a] = __ldg(drow + ix) * s[OFF_G + a];
    }

    float h[H];

    // ----- Layer 1: A -> H, relu -----
    #pragma unroll
    for (int j = 0; j < H; j++) h[j] = s[OFF_B1 + j];
    #pragma unroll 1
    for (int k = 0; k < A; k++) {
        float xk = hp[k];
        const float* w = s + OFF_W1 + k * H;
        #pragma unroll
        for (int j = 0; j < H; j++) h[j] = fmaf(xk, w[j], h[j]);
    }
    #pragma unroll
    for (int j = 0; j < H; j++) hp[j] = fmaxf(h[j], 0.f);

    // ----- Layer 2: H -> H, relu -----
    #pragma unroll
    for (int j = 0; j < H; j++) h[j] = s[OFF_B2 + j];
    #pragma unroll 1
    for (int k = 0; k < H; k++) {
        float xk = hp[k];
        const float* w = s + OFF_W2 + k * H;
        #pragma unroll
        for (int j = 0; j < H; j++) h[j] = fmaf(xk, w[j], h[j]);
    }
    #pragma unroll
    for (int j = 0; j < H; j++) hp[j] = fmaxf(h[j], 0.f);

    // ----- Layer 3: H -> H (relu fused into layer 4 read) -----
    #pragma unroll
    for (int j = 0; j < H; j++) h[j] = s[OFF_B3 + j];
    #pragma unroll 1
    for (int k = 0; k < H; k++) {
        float xk = hp[k];
        const float* w = s + OFF_W3 + k * H;
        #pragma unroll
        for (int j = 0; j < H; j++) h[j] = fmaf(xk, w[j], h[j]);
    }

    // ----- Layer 4: H -> 1 -----
    float acc = s[OFF_B4];
    #pragma unroll
    for (int k = 0; k < H; k++)
        acc = fmaf(fmaxf(h[k], 0.f), s[OFF_W4 + k], acc);

    out[row] = acc;
}

extern "C" void kernel_launch(void* const* d_in, const int* in_sizes, int n_in,
                              void* d_out, int out_size)
{
    const float* data       = (const float*)d_in[0];
    const float* weights    = (const float*)d_in[1];
    const float* W1         = (const float*)d_in[2];
    const float* b1         = (const float*)d_in[3];
    const float* W2         = (const float*)d_in[4];
    const float* b2         = (const float*)d_in[5];
    const float* W3         = (const float*)d_in[6];
    const float* b3         = (const float*)d_in[7];
    const float* W4         = (const float*)d_in[8];
    const float* b4         = (const float*)d_in[9];
    const int*   data_idx   = (const int*)d_in[10];
    const int*   edge_dir   = (const int*)d_in[11];
    const int*   weight_idx = (const int*)d_in[12];
    float* out = (float*)d_out;

    const int n_rows = out_size;  // [B, 1] -> B rows
    const int grid = (n_rows + TPB - 1) / TPB;

    cudaFuncSetAttribute(nodal_mlp_kernel,
                         cudaFuncAttributeMaxDynamicSharedMemorySize, SMEM_BYTES);

    nodal_mlp_kernel<<<grid, TPB, SMEM_BYTES>>>(
        data, weights, W1, b1, W2, b2, W3, b3, W4, b4,
        data_idx, edge_dir, weight_idx, out, n_rows);
}

// round 4
// speedup vs baseline: 3.0648x; 3.0648x over previous
#include <cuda_runtime.h>
#include <cuda_bf16.h>
#include <cstdint>

// nodal_MLP via register-resident mma.sync (bf16 hi/lo 3-term split).
// Each warp owns 16 rows end-to-end (gather -> L1 -> L2 -> L3 -> dot),
// activations never leave registers (C-frag layout == A-frag layout).
// Weights staged once in SMEM (hi/lo bf16, [n][k], padded stride, LDSM-friendly).

#define TPB    256
#define NWARP  8
#define NNODE  256
#define AA     64
#define HH     100
#define NT     13      // 13 n-tiles of 8 -> 104 (cols 100..103 zero-padded)
#define W1S    72      // k-stride (elems) for W1 slab: 64 + 8 pad
#define W2S    120     // k-stride for W2/W3: 112 + 8 pad

// SMEM byte offsets (all 16B aligned)
#define OFF_W1HI 0
#define W1_BYTES (104 * W1S * 2)        // 14976
#define OFF_W1LO (OFF_W1HI + W1_BYTES)
#define OFF_W2HI (OFF_W1LO + W1_BYTES)  // 29952
#define W2_BYTES (104 * W2S * 2)        // 24960
#define OFF_W2LO (OFF_W2HI + W2_BYTES)
#define OFF_W3HI (OFF_W2LO + W2_BYTES)
#define OFF_W3LO (OFF_W3HI + W2_BYTES)
#define OFF_B1   (OFF_W3LO + W2_BYTES)  // 129792, 104 floats
#define OFF_B2   (OFF_B1 + 416)
#define OFF_B3   (OFF_B2 + 416)
#define OFF_W4   (OFF_B3 + 416)
#define OFF_GATE (OFF_W4 + 416)         // 64 floats
#define OFF_IDX  (OFF_GATE + 256)       // 64 ints
#define OFF_B4   (OFF_IDX + 256)
#define SM_TOTAL (OFF_B4 + 16)          // 131984 B

__device__ __forceinline__ uint32_t smem_u32(const void* p) {
    uint32_t a;
    asm("{ .reg .u64 t; cvta.to.shared.u64 t, %1; cvt.u32.u64 %0, t; }" : "=r"(a) : "l"(p));
    return a;
}

#define LDSM_X2(r0, r1, addr) \
    asm volatile("ldmatrix.sync.aligned.m8n8.x2.shared.b16 {%0,%1}, [%2];" \
                 : "=r"(r0), "=r"(r1) : "r"(addr))

#define MMA_BF16(c, a, b0, b1) \
    asm volatile("mma.sync.aligned.m16n8k16.row.col.f32.bf16.bf16.f32 " \
                 "{%0,%1,%2,%3}, {%4,%5,%6,%7}, {%8,%9}, {%0,%1,%2,%3};" \
                 : "+f"((c)[0]), "+f"((c)[1]), "+f"((c)[2]), "+f"((c)[3]) \
                 : "r"((a)[0]), "r"((a)[1]), "r"((a)[2]), "r"((a)[3]), "r"(b0), "r"(b1))

__device__ __forceinline__ uint32_t pack_bf2(__nv_bfloat16 a, __nv_bfloat16 b) {
    __nv_bfloat162 t = __halves2bfloat162(a, b);
    return *reinterpret_cast<uint32_t*>(&t);
}

// split (v0,v1) into packed hi and packed lo bf16x2
__device__ __forceinline__ void split2(float v0, float v1, uint32_t& hi, uint32_t& lo) {
    __nv_bfloat16 h0 = __float2bfloat16(v0);
    __nv_bfloat16 h1 = __float2bfloat16(v1);
    __nv_bfloat16 l0 = __float2bfloat16(v0 - __bfloat162float(h0));
    __nv_bfloat16 l1 = __float2bfloat16(v1 - __bfloat162float(h1));
    hi = pack_bf2(h0, h1);
    lo = pack_bf2(l0, l1);
}

// One layer: acc[13][4] += A[kt] @ W[n-tile j, k-tile kt], 3-term bf16 split.
template<int KT, int STRIDE>
__device__ __forceinline__ void mma_layer(float (&acc)[NT][4],
                                          const uint32_t (&Ahi)[7][4],
                                          const uint32_t (&Alo)[7][4],
                                          uint32_t whi, uint32_t wlo, uint32_t laneoff) {
    #pragma unroll
    for (int kt = 0; kt < KT; kt++) {
        #pragma unroll
        for (int j = 0; j < NT; j++) {
            uint32_t rel = (uint32_t)(j * 8 * STRIDE * 2 + kt * 32) + laneoff;
            uint32_t b0, b1, c0, c1;
            LDSM_X2(b0, b1, whi + rel);
            LDSM_X2(c0, c1, wlo + rel);
            MMA_BF16(acc[j], Ahi[kt], b0, b1);   // ah*bh
            MMA_BF16(acc[j], Alo[kt], b0, b1);   // al*bh
            MMA_BF16(acc[j], Ahi[kt], c0, c1);   // ah*bl
        }
    }
}

// relu(acc + bias) -> next-layer A fragments (hi/lo), reset acc.
__device__ __forceinline__ void build_A(float (&acc)[NT][4],
                                        uint32_t (&Ahi)[7][4], uint32_t (&Alo)[7][4],
                                        const float* bias, int m2) {
    #pragma unroll
    for (int j = 0; j < NT; j++) {
        float2 b = *reinterpret_cast<const float2*>(bias + 8 * j + m2);
        float v0 = fmaxf(acc[j][0] + b.x, 0.f);
        float v1 = fmaxf(acc[j][1] + b.y, 0.f);
        float v2 = fmaxf(acc[j][2] + b.x, 0.f);
        float v3 = fmaxf(acc[j][3] + b.y, 0.f);
        int kt = j >> 1, o = (j & 1) << 1;
        split2(v0, v1, Ahi[kt][o],     Alo[kt][o]);
        split2(v2, v3, Ahi[kt][o + 1], Alo[kt][o + 1]);
        acc[j][0] = acc[j][1] = acc[j][2] = acc[j][3] = 0.f;
    }
    Ahi[6][2] = Ahi[6][3] = Alo[6][2] = Alo[6][3] = 0u;  // k 104..111 pad
}

extern __shared__ char sm[];

__global__ void __launch_bounds__(TPB, 1) nodal_mlp_hmma(
    const float* __restrict__ data, const float* __restrict__ weights,
    const float* __restrict__ W1, const float* __restrict__ b1,
    const float* __restrict__ W2, const float* __restrict__ b2,
    const float* __restrict__ W3, const float* __restrict__ b3,
    const float* __restrict__ W4, const float* __restrict__ b4,
    const int* __restrict__ data_idx, const int* __restrict__ edge_dir,
    const int* __restrict__ weight_idx,
    float* __restrict__ out, int n_rows)
{
    const int t = threadIdx.x;

    // ---- stage weights (once per CTA) ----
    for (int i = t; i < SM_TOTAL / 4; i += TPB)
        reinterpret_cast<uint32_t*>(sm)[i] = 0;
    __syncthreads();

    for (int i = t; i < AA * HH; i += TPB) {
        int k = i / HH, n = i % HH;
        float v = W1[i];
        __nv_bfloat16 h = __float2bfloat16(v);
        __nv_bfloat16 l = __float2bfloat16(v - __bfloat162float(h));
        *reinterpret_cast<__nv_bfloat16*>(sm + OFF_W1HI + (n * W1S + k) * 2) = h;
        *reinterpret_cast<__nv_bfloat16*>(sm + OFF_W1LO + (n * W1S + k) * 2) = l;
    }
    for (int i = t; i < HH * HH; i += TPB) {
        int k = i / HH, n = i % HH;
        int o = (n * W2S + k) * 2;
        float v = W2[i];
        __nv_bfloat16 h = __float2bfloat16(v);
        *reinterpret_cast<__nv_bfloat16*>(sm + OFF_W2HI + o) = h;
        *reinterpret_cast<__nv_bfloat16*>(sm + OFF_W2LO + o) =
            __float2bfloat16(v - __bfloat162float(h));
        v = W3[i];
        h = __float2bfloat16(v);
        *reinterpret_cast<__nv_bfloat16*>(sm + OFF_W3HI + o) = h;
        *reinterpret_cast<__nv_bfloat16*>(sm + OFF_W3LO + o) =
            __float2bfloat16(v - __bfloat162float(h));
    }
    if (t < HH) {
        reinterpret_cast<float*>(sm + OFF_B1)[t] = b1[t];
        reinterpret_cast<float*>(sm + OFF_B2)[t] = b2[t];
        reinterpret_cast<float*>(sm + OFF_B3)[t] = b3[t];
        reinterpret_cast<float*>(sm + OFF_W4)[t] = W4[t];
    }
    if (t < AA) {
        reinterpret_cast<int*>(sm + OFF_IDX)[t] = data_idx[t];
        float g = weights[weight_idx[t]] * (float)edge_dir[t];
        reinterpret_cast<float*>(sm + OFF_GATE)[t] = g > 0.f ? g : 0.f;
    }
    if (t == 0) reinterpret_cast<float*>(sm + OFF_B4)[0] = b4[0];
    __syncthreads();

    const uint32_t sb = smem_u32(sm);
    const int lane = t & 31;
    const int warp = t >> 5;
    const int m = lane & 3;
    const int m2 = m * 2;
    const int qrow = lane >> 2;
    const uint32_t loff1 = (uint32_t)(((lane & 7) * W1S + ((lane & 15) >> 3) * 8) * 2);
    const uint32_t loff2 = (uint32_t)(((lane & 7) * W2S + ((lane & 15) >> 3) * 8) * 2);

    const float* gate = reinterpret_cast<const float*>(sm + OFF_GATE);
    const int*   sidx = reinterpret_cast<const int*>(sm + OFF_IDX);
    const float* sb1  = reinterpret_cast<const float*>(sm + OFF_B1);
    const float* sb2  = reinterpret_cast<const float*>(sm + OFF_B2);
    const float* sb3  = reinterpret_cast<const float*>(sm + OFF_B3);
    const float* sw4  = reinterpret_cast<const float*>(sm + OFF_W4);
    const float  b4v  = reinterpret_cast<const float*>(sm + OFF_B4)[0];

    const int n_wt = (n_rows + 15) >> 4;         // 16-row warp tiles
    const int gw = blockIdx.x * NWARP + warp;
    const int wstride = gridDim.x * NWARP;

    for (int wt = gw; wt < n_wt; wt += wstride) {
        const int r0 = wt * 16 + qrow;
        const int r1 = r0 + 8;
        const bool ok0 = r0 < n_rows, ok1 = r1 < n_rows;
        const float* dr0 = data + (size_t)(ok0 ? r0 : 0) * NNODE;
        const float* dr1 = data + (size_t)(ok1 ? r1 : 0) * NNODE;

        uint32_t Ahi[7][4], Alo[7][4];

        // ---- gather + gate -> X fragments (4 k-tiles) ----
        #pragma unroll
        for (int kt = 0; kt < 4; kt++) {
            int k0 = kt * 16 + m2;
            int i0 = sidx[k0], i1 = sidx[k0 + 1], i2 = sidx[k0 + 8], i3 = sidx[k0 + 9];
            float g0 = gate[k0], g1 = gate[k0 + 1], g2 = gate[k0 + 8], g3 = gate[k0 + 9];
            float v00 = ok0 ? dr0[i0] * g0 : 0.f;
            float v01 = ok0 ? dr0[i1] * g1 : 0.f;
            float v02 = ok0 ? dr0[i2] * g2 : 0.f;
            float v03 = ok0 ? dr0[i3] * g3 : 0.f;
            float v10 = ok1 ? dr1[i0] * g0 : 0.f;
            float v11 = ok1 ? dr1[i1] * g1 : 0.f;
            float v12 = ok1 ? dr1[i2] * g2 : 0.f;
            float v13 = ok1 ? dr1[i3] * g3 : 0.f;
            split2(v00, v01, Ahi[kt][0], Alo[kt][0]);
            split2(v10, v11, Ahi[kt][1], Alo[kt][1]);
            split2(v02, v03, Ahi[kt][2], Alo[kt][2]);
            split2(v12, v13, Ahi[kt][3], Alo[kt][3]);
        }

        float acc[NT][4];
        #pragma unroll
        for (int j = 0; j < NT; j++)
            acc[j][0] = acc[j][1] = acc[j][2] = acc[j][3] = 0.f;

        // ---- layers ----
        mma_layer<4, W1S>(acc, Ahi, Alo, sb + OFF_W1HI, sb + OFF_W1LO, loff1);
        build_A(acc, Ahi, Alo, sb1, m2);
        mma_layer<7, W2S>(acc, Ahi, Alo, sb + OFF_W2HI, sb + OFF_W2LO, loff2);
        build_A(acc, Ahi, Alo, sb2, m2);
        mma_layer<7, W2S>(acc, Ahi, Alo, sb + OFF_W3HI, sb + OFF_W3LO, loff2);

        // ---- layer 4: relu + dot + quad reduce ----
        float s0 = 0.f, s1 = 0.f;
        #pragma unroll
        for (int j = 0; j < NT; j++) {
            float2 b = *reinterpret_cast<const float2*>(sb3 + 8 * j + m2);
            float2 w = *reinterpret_cast<const float2*>(sw4 + 8 * j + m2);
            s0 = fmaf(fmaxf(acc[j][0] + b.x, 0.f), w.x, s0);
            s0 = fmaf(fmaxf(acc[j][1] + b.y, 0.f), w.y, s0);
            s1 = fmaf(fmaxf(acc[j][2] + b.x, 0.f), w.x, s1);
            s1 = fmaf(fmaxf(acc[j][3] + b.y, 0.f), w.y, s1);
        }
        s0 += __shfl_xor_sync(0xFFFFFFFFu, s0, 1);
        s0 += __shfl_xor_sync(0xFFFFFFFFu, s0, 2);
        s1 += __shfl_xor_sync(0xFFFFFFFFu, s1, 1);
        s1 += __shfl_xor_sync(0xFFFFFFFFu, s1, 2);
        if (m == 0) {
            if (ok0) out[r0] = s0 + b4v;
            if (ok1) out[r1] = s1 + b4v;
        }
    }
}

extern "C" void kernel_launch(void* const* d_in, const int* in_sizes, int n_in,
                              void* d_out, int out_size)
{
    const float* data       = (const float*)d_in[0];
    const float* weights    = (const float*)d_in[1];
    const float* W1         = (const float*)d_in[2];
    const float* b1         = (const float*)d_in[3];
    const float* W2         = (const float*)d_in[4];
    const float* b2         = (const float*)d_in[5];
    const float* W3         = (const float*)d_in[6];
    const float* b3         = (const float*)d_in[7];
    const float* W4         = (const float*)d_in[8];
    const float* b4         = (const float*)d_in[9];
    const int*   data_idx   = (const int*)d_in[10];
    const int*   edge_dir   = (const int*)d_in[11];
    const int*   weight_idx = (const int*)d_in[12];
    float* out = (float*)d_out;

    const int n_rows = out_size;

    cudaFuncSetAttribute(nodal_mlp_hmma,
                         cudaFuncAttributeMaxDynamicSharedMemorySize, SM_TOTAL);

    nodal_mlp_hmma<<<148, TPB, SM_TOTAL>>>(
        data, weights, W1, b1, W2, b2, W3, b3, W4, b4,
        data_idx, edge_dir, weight_idx, out, n_rows);
}

// round 7
// speedup vs baseline: 4.8981x; 1.5982x over previous
#include <cuda_runtime.h>
#include <cuda_bf16.h>
#include <cstdint>

// nodal_MLP via register-resident mma.sync (bf16 hi/lo 3-term split).
// R5: sorted gather indices (joint permutation of data_idx/gate/W1-rows is an
// identity) -> gather LDGs read consecutive columns; LDSM.x4 interleaved hi/lo.

#define TPB    256
#define NWARP  8
#define NNODE  256
#define AA     64
#define HH     100
#define NT     13      // 13 n-tiles of 8 -> 104 (cols 100..103 zero-padded)
#define W1S    72      // k-stride (elems) for W1 slab: 64 + 8 pad
#define W2S    120     // k-stride for W2/W3: 112 + 8 pad

// SMEM byte offsets (all 16B aligned)
#define OFF_W1HI 0
#define W1_BYTES (104 * W1S * 2)        // 14976
#define OFF_W1LO (OFF_W1HI + W1_BYTES)
#define OFF_W2HI (OFF_W1LO + W1_BYTES)
#define W2_BYTES (104 * W2S * 2)        // 24960
#define OFF_W2LO (OFF_W2HI + W2_BYTES)
#define OFF_W3HI (OFF_W2LO + W2_BYTES)
#define OFF_W3LO (OFF_W3HI + W2_BYTES)
#define OFF_B1   (OFF_W3LO + W2_BYTES)  // 104 floats each
#define OFF_B2   (OFF_B1 + 416)
#define OFF_B3   (OFF_B2 + 416)
#define OFF_W4   (OFF_B3 + 416)
#define OFF_GATE (OFF_W4 + 416)         // 64 floats (sorted order)
#define OFF_IDX  (OFF_GATE + 256)       // 64 ints   (sorted order)
#define OFF_SCR  (OFF_IDX + 256)        // 64 ints raw idx scratch
#define OFF_RANK (OFF_SCR + 256)        // 64 ints: rank of original k
#define OFF_B4   (OFF_RANK + 256)
#define SM_TOTAL (OFF_B4 + 16)

__device__ __forceinline__ uint32_t smem_u32(const void* p) {
    uint32_t a;
    asm("{ .reg .u64 t; cvta.to.shared.u64 t, %1; cvt.u32.u64 %0, t; }" : "=r"(a) : "l"(p));
    return a;
}

// x4: matrices 0,1 from hi slab (lanes 0..15), 2,3 from lo slab (lanes 16..31,
// delta folded into the per-lane offset).
#define LDSM_X4(r0, r1, r2, r3, addr) \
    asm volatile("ldmatrix.sync.aligned.m8n8.x4.shared.b16 {%0,%1,%2,%3}, [%4];" \
                 : "=r"(r0), "=r"(r1), "=r"(r2), "=r"(r3) : "r"(addr))

#define MMA_BF16(c, a, b0, b1) \
    asm volatile("mma.sync.aligned.m16n8k16.row.col.f32.bf16.bf16.f32 " \
                 "{%0,%1,%2,%3}, {%4,%5,%6,%7}, {%8,%9}, {%0,%1,%2,%3};" \
                 : "+f"((c)[0]), "+f"((c)[1]), "+f"((c)[2]), "+f"((c)[3]) \
                 : "r"((a)[0]), "r"((a)[1]), "r"((a)[2]), "r"((a)[3]), "r"(b0), "r"(b1))

__device__ __forceinline__ uint32_t pack_bf2(__nv_bfloat16 a, __nv_bfloat16 b) {
    __nv_bfloat162 t = __halves2bfloat162(a, b);
    return *reinterpret_cast<uint32_t*>(&t);
}
__device__ __forceinline__ void split2(float v0, float v1, uint32_t& hi, uint32_t& lo) {
    __nv_bfloat16 h0 = __float2bfloat16(v0);
    __nv_bfloat16 h1 = __float2bfloat16(v1);
    __nv_bfloat16 l0 = __float2bfloat16(v0 - __bfloat162float(h0));
    __nv_bfloat16 l1 = __float2bfloat16(v1 - __bfloat162float(h1));
    hi = pack_bf2(h0, h1);
    lo = pack_bf2(l0, l1);
}

// One layer: acc[13][4] += A @ W, 3-term bf16 split, B hi+lo via one LDSM.x4.
template<int KT, int STRIDE>
__device__ __forceinline__ void mma_layer(float (&acc)[NT][4],
                                          const uint32_t (&Ahi)[7][4],
                                          const uint32_t (&Alo)[7][4],
                                          uint32_t whi, uint32_t laneoff) {
    #pragma unroll
    for (int kt = 0; kt < KT; kt++) {
        #pragma unroll
        for (int j = 0; j < NT; j++) {
            uint32_t rel = (uint32_t)(j * 8 * STRIDE * 2 + kt * 32) + laneoff;
            uint32_t b0, b1, c0, c1;
            LDSM_X4(b0, b1, c0, c1, whi + rel);
            MMA_BF16(acc[j], Ahi[kt], b0, b1);   // ah*bh
            MMA_BF16(acc[j], Alo[kt], b0, b1);   // al*bh
            MMA_BF16(acc[j], Ahi[kt], c0, c1);   // ah*bl
        }
    }
}

// relu(acc + bias) -> next-layer A fragments (hi/lo), reset acc.
__device__ __forceinline__ void build_A(float (&acc)[NT][4],
                                        uint32_t (&Ahi)[7][4], uint32_t (&Alo)[7][4],
                                        const float* bias, int m2) {
    #pragma unroll
    for (int j = 0; j < NT; j++) {
        float2 b = *reinterpret_cast<const float2*>(bias + 8 * j + m2);
        float v0 = fmaxf(acc[j][0] + b.x, 0.f);
        float v1 = fmaxf(acc[j][1] + b.y, 0.f);
        float v2 = fmaxf(acc[j][2] + b.x, 0.f);
        float v3 = fmaxf(acc[j][3] + b.y, 0.f);
        int kt = j >> 1, o = (j & 1) << 1;
        split2(v0, v1, Ahi[kt][o],     Alo[kt][o]);
        split2(v2, v3, Ahi[kt][o + 1], Alo[kt][o + 1]);
        acc[j][0] = acc[j][1] = acc[j][2] = acc[j][3] = 0.f;
    }
    Ahi[6][2] = Ahi[6][3] = Alo[6][2] = Alo[6][3] = 0u;  // k 104..111 pad
}

extern __shared__ char sm[];

__global__ void __launch_bounds__(TPB, 1) nodal_mlp_hmma(
    const float* __restrict__ data, const float* __restrict__ weights,
    const float* __restrict__ W1, const float* __restrict__ b1,
    const float* __restrict__ W2, const float* __restrict__ b2,
    const float* __restrict__ W3, const float* __restrict__ b3,
    const float* __restrict__ W4, const float* __restrict__ b4,
    const int* __restrict__ data_idx, const int* __restrict__ edge_dir,
    const int* __restrict__ weight_idx,
    float* __restrict__ out, int n_rows)
{
    const int t = threadIdx.x;

    // ---- zero smem ----
    for (int i = t; i < SM_TOTAL / 4; i += TPB)
        reinterpret_cast<uint32_t*>(sm)[i] = 0;
    __syncthreads();

    // ---- sort indices: rank of each original k among data_idx (ties by pos) ----
    int* scr  = reinterpret_cast<int*>(sm + OFF_SCR);
    int* rnk  = reinterpret_cast<int*>(sm + OFF_RANK);
    if (t < AA) scr[t] = data_idx[t];
    __syncthreads();
    if (t < AA) {
        int my = scr[t];
        int r = 0;
        #pragma unroll
        for (int j = 0; j < AA; j++) {
            int o = scr[j];
            r += (o < my) || (o == my && j < t);
        }
        rnk[t] = r;
        reinterpret_cast<int*>(sm + OFF_IDX)[r] = my;
        float g = weights[weight_idx[t]] * (float)edge_dir[t];
        reinterpret_cast<float*>(sm + OFF_GATE)[r] = g > 0.f ? g : 0.f;
    }
    __syncthreads();

    // ---- stage weights (once per CTA); W1 rows permuted by rank ----
    for (int i = t; i < AA * HH; i += TPB) {
        int k = rnk[i / HH], n = i % HH;
        float v = W1[i];
        __nv_bfloat16 h = __float2bfloat16(v);
        __nv_bfloat16 l = __float2bfloat16(v - __bfloat162float(h));
        *reinterpret_cast<__nv_bfloat16*>(sm + OFF_W1HI + (n * W1S + k) * 2) = h;
        *reinterpret_cast<__nv_bfloat16*>(sm + OFF_W1LO + (n * W1S + k) * 2) = l;
    }
    for (int i = t; i < HH * HH; i += TPB) {
        int k = i / HH, n = i % HH;
        int o = (n * W2S + k) * 2;
        float v = W2[i];
        __nv_bfloat16 h = __float2bfloat16(v);
        *reinterpret_cast<__nv_bfloat16*>(sm + OFF_W2HI + o) = h;
        *reinterpret_cast<__nv_bfloat16*>(sm + OFF_W2LO + o) =
            __float2bfloat16(v - __bfloat162float(h));
        v = W3[i];
        h = __float2bfloat16(v);
        *reinterpret_cast<__nv_bfloat16*>(sm + OFF_W3HI + o) = h;
        *reinterpret_cast<__nv_bfloat16*>(sm + OFF_W3LO + o) =
            __float2bfloat16(v - __bfloat162float(h));
    }
    if (t < HH) {
        reinterpret_cast<float*>(sm + OFF_B1)[t] = b1[t];
        reinterpret_cast<float*>(sm + OFF_B2)[t] = b2[t];
        reinterpret_cast<float*>(sm + OFF_B3)[t] = b3[t];
        reinterpret_cast<float*>(sm + OFF_W4)[t] = W4[t];
    }
    if (t == 0) reinterpret_cast<float*>(sm + OFF_B4)[0] = b4[0];
    __syncthreads();

    const uint32_t sb = smem_u32(sm);
    const int lane = t & 31;
    const int warp = t >> 5;
    const int m = lane & 3;
    const int m2 = m * 2;
    const int qrow = lane >> 2;
    // ldmatrix.x4 lane offsets: lanes 0-15 -> hi slab, 16-31 -> lo slab
    const uint32_t loff1 = (uint32_t)(((lane & 7) * W1S + ((lane >> 3) & 1) * 8) * 2
                                      + ((lane >> 4) & 1) * W1_BYTES);
    const uint32_t loff2 = (uint32_t)(((lane & 7) * W2S + ((lane >> 3) & 1) * 8) * 2
                                      + ((lane >> 4) & 1) * W2_BYTES);

    const float* gate = reinterpret_cast<const float*>(sm + OFF_GATE);
    const int*   sidx = reinterpret_cast<const int*>(sm + OFF_IDX);
    const float* sb1  = reinterpret_cast<const float*>(sm + OFF_B1);
    const float* sb2  = reinterpret_cast<const float*>(sm + OFF_B2);
    const float* sb3  = reinterpret_cast<const float*>(sm + OFF_B3);
    const float* sw4  = reinterpret_cast<const float*>(sm + OFF_W4);
    const float  b4v  = reinterpret_cast<const float*>(sm + OFF_B4)[0];

    const int n_wt = (n_rows + 15) >> 4;         // 16-row warp tiles
    const int gw = blockIdx.x * NWARP + warp;
    const int wstride = gridDim.x * NWARP;

    for (int wt = gw; wt < n_wt; wt += wstride) {
        const int r0 = wt * 16 + qrow;
        const int r1 = r0 + 8;
        const bool ok0 = r0 < n_rows, ok1 = r1 < n_rows;
        const float* dr0 = data + (size_t)(ok0 ? r0 : 0) * NNODE;
        const float* dr1 = data + (size_t)(ok1 ? r1 : 0) * NNODE;

        uint32_t Ahi[7][4], Alo[7][4];

        // ---- gather + gate -> X fragments (sorted idx: consecutive cols/LDG) ----
        #pragma unroll
        for (int kt = 0; kt < 4; kt++) {
            int k0 = kt * 16 + m2;
            int i0 = sidx[k0], i1 = sidx[k0 + 1], i2 = sidx[k0 + 8], i3 = sidx[k0 + 9];
            float g0 = gate[k0], g1 = gate[k0 + 1], g2 = gate[k0 + 8], g3 = gate[k0 + 9];
            float v00 = ok0 ? dr0[i0] * g0 : 0.f;
            float v01 = ok0 ? dr0[i1] * g1 : 0.f;
            float v02 = ok0 ? dr0[i2] * g2 : 0.f;
            float v03 = ok0 ? dr0[i3] * g3 : 0.f;
            float v10 = ok1 ? dr1[i0] * g0 : 0.f;
            float v11 = ok1 ? dr1[i1] * g1 : 0.f;
            float v12 = ok1 ? dr1[i2] * g2 : 0.f;
            float v13 = ok1 ? dr1[i3] * g3 : 0.f;
            split2(v00, v01, Ahi[kt][0], Alo[kt][0]);
            split2(v10, v11, Ahi[kt][1], Alo[kt][1]);
            split2(v02, v03, Ahi[kt][2], Alo[kt][2]);
            split2(v12, v13, Ahi[kt][3], Alo[kt][3]);
        }

        float acc[NT][4];
        #pragma unroll
        for (int j = 0; j < NT; j++)
            acc[j][0] = acc[j][1] = acc[j][2] = acc[j][3] = 0.f;

        // ---- layers ----
        mma_layer<4, W1S>(acc, Ahi, Alo, sb + OFF_W1HI, loff1);
        build_A(acc, Ahi, Alo, sb1, m2);
        mma_layer<7, W2S>(acc, Ahi, Alo, sb + OFF_W2HI, loff2);
        build_A(acc, Ahi, Alo, sb2, m2);
        mma_layer<7, W2S>(acc, Ahi, Alo, sb + OFF_W3HI, loff2);

        // ---- layer 4: relu + dot + quad reduce ----
        float s0 = 0.f, s1 = 0.f;
        #pragma unroll
        for (int j = 0; j < NT; j++) {
            float2 b = *reinterpret_cast<const float2*>(sb3 + 8 * j + m2);
            float2 w = *reinterpret_cast<const float2*>(sw4 + 8 * j + m2);
            s0 = fmaf(fmaxf(acc[j][0] + b.x, 0.f), w.x, s0);
            s0 = fmaf(fmaxf(acc[j][1] + b.y, 0.f), w.y, s0);
            s1 = fmaf(fmaxf(acc[j][2] + b.x, 0.f), w.x, s1);
            s1 = fmaf(fmaxf(acc[j][3] + b.y, 0.f), w.y, s1);
        }
        s0 += __shfl_xor_sync(0xFFFFFFFFu, s0, 1);
        s0 += __shfl_xor_sync(0xFFFFFFFFu, s0, 2);
        s1 += __shfl_xor_sync(0xFFFFFFFFu, s1, 1);
        s1 += __shfl_xor_sync(0xFFFFFFFFu, s1, 2);
        if (m == 0) {
            if (ok0) out[r0] = s0 + b4v;
            if (ok1) out[r1] = s1 + b4v;
        }
    }
}

extern "C" void kernel_launch(void* const* d_in, const int* in_sizes, int n_in,
                              void* d_out, int out_size)
{
    const float* data       = (const float*)d_in[0];
    const float* weights    = (const float*)d_in[1];
    const float* W1         = (const float*)d_in[2];
    const float* b1         = (const float*)d_in[3];
    const float* W2         = (const float*)d_in[4];
    const float* b2         = (const float*)d_in[5];
    const float* W3         = (const float*)d_in[6];
    const float* b3         = (const float*)d_in[7];
    const float* W4         = (const float*)d_in[8];
    const float* b4         = (const float*)d_in[9];
    const int*   data_idx   = (const int*)d_in[10];
    const int*   edge_dir   = (const int*)d_in[11];
    const int*   weight_idx = (const int*)d_in[12];
    float* out = (float*)d_out;

    const int n_rows = out_size;

    cudaFuncSetAttribute(nodal_mlp_hmma,
                         cudaFuncAttributeMaxDynamicSharedMemorySize, SM_TOTAL);

    nodal_mlp_hmma<<<148, TPB, SM_TOTAL>>>(
        data, weights, W1, b1, W2, b2, W3, b3, W4, b4,
        data_idx, edge_dir, weight_idx, out, n_rows);
}